// round 14
// baseline (speedup 1.0000x reference)
#include <cuda_runtime.h>
#include <math.h>

// ---------------- problem constants ----------------
#define DIN     32
#define KLEN    512
#define PDIM    64
#define DMODEL  128
#define NLAYERS 4
#define PLEN    8
#define STRIDE  4
#define DI2     256
#define DSTATE  16
#define DCONV   4
#define DTRANK  8
#define NSEQ    127
#define BATCH   32
#define MROWS   (BATCH*PDIM)     // 2048
#define RTOT    (MROWS*NSEQ)     // 260096

// ---------------- scratch ----------------
__device__ float g_h[BATCH*KLEN*PDIM];
__device__ float g_e[RTOT*DMODEL];
__device__ float g_rstd[RTOT];
__device__ float g_uz[RTOT*2*DI2];
__device__ float g_y[RTOT*DI2];
__device__ unsigned g_wins[NLAYERS*65536];   // in_w bf16-pair images
__device__ unsigned g_wouts[NLAYERS*32768];  // out_w bf16-pair images
__device__ float g_val[MROWS];

// ---------------- helpers ----------------
__device__ __forceinline__ unsigned bf16pair(float v0, float v1) {
    unsigned p;
    asm("cvt.rn.bf16x2.f32 %0, %1, %2;" : "=r"(p) : "f"(v1), "f"(v0));
    return p;
}
__device__ __forceinline__ void bf16split(float v0, float v1, unsigned& hp, unsigned& lp) {
    hp = bf16pair(v0, v1);
    float r0 = v0 - __uint_as_float(hp << 16);
    float r1 = v1 - __uint_as_float(hp & 0xffff0000u);
    lp = bf16pair(r0, r1);
}
__device__ __forceinline__ void mma_bf16(float* d, const unsigned* a, const unsigned* b) {
    asm volatile(
        "mma.sync.aligned.m16n8k16.row.col.f32.bf16.bf16.f32 "
        "{%0,%1,%2,%3}, {%4,%5,%6,%7}, {%8,%9}, {%0,%1,%2,%3};\n"
        : "+f"(d[0]), "+f"(d[1]), "+f"(d[2]), "+f"(d[3])
        : "r"(a[0]), "r"(a[1]), "r"(a[2]), "r"(a[3]), "r"(b[0]), "r"(b[1]));
}
__device__ __forceinline__ void cp16(unsigned smem, const void* gptr) {
    asm volatile("cp.async.cg.shared.global [%0], [%1], 16;\n" :: "r"(smem), "l"(gptr));
}
__device__ __forceinline__ unsigned s2u(const void* p) {
    return (unsigned)__cvta_generic_to_shared(p);
}
template<int NN> __device__ __forceinline__ void cpwait() {
    asm volatile("cp.async.wait_group %0;\n" :: "n"(NN));
}
// ---- packed f32x2 (sm_100+) ----
typedef unsigned long long u64;
__device__ __forceinline__ u64 pack2(float lo, float hi) {
    u64 r; asm("mov.b64 %0, {%1, %2};" : "=l"(r) : "f"(lo), "f"(hi)); return r;
}
__device__ __forceinline__ void unpack2(u64 v, float& lo, float& hi) {
    asm("mov.b64 {%0, %1}, %2;" : "=f"(lo), "=f"(hi) : "l"(v));
}
__device__ __forceinline__ u64 fma2(u64 a, u64 b, u64 c) {
    u64 d; asm("fma.rn.f32x2 %0, %1, %2, %3;" : "=l"(d) : "l"(a), "l"(b), "l"(c)); return d;
}
__device__ __forceinline__ u64 mul2(u64 a, u64 b) {
    u64 d; asm("mul.rn.f32x2 %0, %1, %2;" : "=l"(d) : "l"(a), "l"(b)); return d;
}

// ---------------- 1. weight pre-split (launch #0) ----------------
__global__ void k_wsplit(const float* __restrict__ in_w, const float* __restrict__ out_w) {
    int idx = blockIdx.x*256 + threadIdx.x;
    if (idx < NLAYERS*32768) {               // in_w: 64 kpairs x 512 n per layer
        int l = idx >> 15;
        int e = idx & 32767;
        int pg = e >> 9, n = e & 511;
        const float* W = in_w + (size_t)l*65536;
        float v0 = W[(2*pg)*512 + n];
        float v1 = W[(2*pg+1)*512 + n];
        unsigned hp, lp; bf16split(v0, v1, hp, lp);
        int bx = n >> 7, nl = n & 127;
        int kt = pg >> 3, pl = pg & 7;
        int slotH = (pl >> 2) & 1;
        size_t base = (size_t)l*65536 + (size_t)(bx*8 + kt)*2048 + (size_t)(nl*4 + (pl & 3))*4;
        g_wins[base + slotH]     = hp;
        g_wins[base + 2 + slotH] = lp;
    } else {
        int idx2 = idx - NLAYERS*32768;
        if (idx2 < NLAYERS*16384) {          // out_w: 128 kpairs x 128 n per layer
            int l = idx2 >> 14;
            int e = idx2 & 16383;
            int pg = e >> 7, n = e & 127;
            const float* W = out_w + (size_t)l*32768;
            float v0 = W[(2*pg)*128 + n];
            float v1 = W[(2*pg+1)*128 + n];
            unsigned hp, lp; bf16split(v0, v1, hp, lp);
            int kt = pg >> 3, pl = pg & 7;
            int slotH = (pl >> 2) & 1;
            size_t base = (size_t)l*32768 + (size_t)kt*2048 + (size_t)(n*4 + (pl & 3))*4;
            g_wouts[base + slotH]     = hp;
            g_wouts[base + 2 + slotH] = lp;
        }
    }
}

// ---------------- 2. x@proj_w + b, LayerNorm (launch #1) ----------------
__global__ void k_proj_ln(const float* __restrict__ x, const float* __restrict__ pw,
                          const float* __restrict__ pb, const float* __restrict__ lw,
                          const float* __restrict__ lb) {
    int row = blockIdx.x;
    int t = threadIdx.x;
    __shared__ float xs[DIN];
    __shared__ float r1[64], r2[64];
    if (t < DIN) xs[t] = x[row*DIN + t];
    __syncthreads();
    float acc = pb[t];
#pragma unroll
    for (int i = 0; i < DIN; i++) acc = fmaf(xs[i], pw[i*PDIM + t], acc);
    r1[t] = acc; r2[t] = acc*acc;
    __syncthreads();
    for (int o = 32; o; o >>= 1) {
        if (t < o) { r1[t] += r1[t+o]; r2[t] += r2[t+o]; }
        __syncthreads();
    }
    float mu  = r1[0] * (1.f/64.f);
    float var = r2[0] * (1.f/64.f) - mu*mu;
    g_h[row*PDIM + t] = (acc - mu) * rsqrtf(var + 1e-5f) * lw[t] + lb[t];
}

// ---------------- 3. patch embed + fused rms (launch #2) ----------------
__global__ void k_patch(const float* __restrict__ pw, const float* __restrict__ pb) {
    int n = blockIdx.x, m = blockIdx.y;
    int t = threadIdx.x;                 // 0..127
    int w = t >> 5, lane = t & 31;
    __shared__ float hv[PLEN];
    __shared__ float red[4];
    int b = m >> 6, pd = m & 63;
    if (t < PLEN) hv[t] = g_h[(b*KLEN + n*STRIDE + t)*PDIM + pd];
    __syncthreads();
    float acc = pb[t];
#pragma unroll
    for (int p = 0; p < PLEN; p++) acc = fmaf(hv[p], pw[p*DMODEL + t], acc);
    g_e[((size_t)m*NSEQ + n)*DMODEL + t] = acc;
    float s = acc*acc;
#pragma unroll
    for (int o = 16; o; o >>= 1) s += __shfl_xor_sync(0xffffffff, s, o);
    if (lane == 0) red[w] = s;
    __syncthreads();
    if (t == 0) {
        float ss = red[0] + red[1] + red[2] + red[3];
        g_rstd[(size_t)m*NSEQ + n] = rsqrtf(ss*(1.f/DMODEL) + 1e-5f);
    }
}

// ---------------- 4. bf16x2 (3-product) GEMM, cp.async double-buffered ----------------
template<int MODE>
__global__ __launch_bounds__(256, 2) void k_gemm_tc(const float* __restrict__ A,
                                                    const float* __restrict__ colScale,
                                                    const unsigned* __restrict__ Bp,
                                                    float* __restrict__ C) {
    constexpr int N  = (MODE == 0) ? 512 : 128;
    constexpr int K  = (MODE == 0) ? 128 : 256;
    constexpr int KT = K/16;

    __shared__ __align__(16) unsigned AsH[2][1024], AsL[2][1024], Bs[2][2048];

    int tid = threadIdx.x;
    int wid = tid >> 5, lane = tid & 31;
    int wm = wid >> 2, wn = wid & 3;
    int g = lane >> 2, tig = lane & 3;
    int row0 = blockIdx.y * 128;
    int bx = blockIdx.x;
    const float4* Bg = (const float4*)Bp + (size_t)bx*KT*512;

    float acc[4][4][4];
#pragma unroll
    for (int mt = 0; mt < 4; mt++)
#pragma unroll
        for (int nt = 0; nt < 4; nt++)
#pragma unroll
            for (int j = 0; j < 4; j++) acc[mt][nt][j] = 0.f;

    int rA = tid >> 2;
    int kq = (tid & 3)*4;
    int p0 = kq >> 1;

    int rg0 = (rA & 7) | ((rA >> 4) << 3);
    int rb3 = (rA >> 3) & 1;
    int sw  = (rg0 >> 1) & 3;
    int a0 = (((p0 & 3) ^ sw) << 2) + (rb3 | (((p0 >> 2) & 1) << 1));
    int p1 = p0 + 1;
    int a1 = (((p1 & 3) ^ sw) << 2) + (rb3 | (((p1 >> 2) & 1) << 1));

    float rs0 = 1.f, rs1 = 1.f;
    if (MODE == 0) { rs0 = g_rstd[row0 + rA]; rs1 = g_rstd[row0 + rA + 64]; }

    cp16(s2u(&Bs[0][tid*4]),       Bg + tid);
    cp16(s2u(&Bs[0][(tid+256)*4]), Bg + tid + 256);
    asm volatile("cp.async.commit_group;\n");
    float4 pa0 = *(const float4*)&A[(size_t)(row0 + rA)*K + kq];
    float4 pa1 = *(const float4*)&A[(size_t)(row0 + rA + 64)*K + kq];

    for (int kt = 0; kt < KT; kt++) {
        int cur = kt & 1, nxt = cur ^ 1;
        bool pre = (kt + 1 < KT);
        if (pre) {
            const float4* src = Bg + (size_t)(kt+1)*512;
            cp16(s2u(&Bs[nxt][tid*4]),       src + tid);
            cp16(s2u(&Bs[nxt][(tid+256)*4]), src + tid + 256);
            asm volatile("cp.async.commit_group;\n");
        }
        float4 na0 = pa0, na1 = pa1;
        if (pre) {
            int k0n = (kt+1)*16;
            na0 = *(const float4*)&A[(size_t)(row0 + rA)*K + k0n + kq];
            na1 = *(const float4*)&A[(size_t)(row0 + rA + 64)*K + k0n + kq];
        }
        {
            float4 cs = make_float4(1.f, 1.f, 1.f, 1.f);
            if (MODE == 0) cs = *(const float4*)&colScale[kt*16 + kq];
            {
                float v0 = pa0.x, v1 = pa0.y, v2 = pa0.z, v3 = pa0.w;
                if (MODE == 0) { v0 *= rs0*cs.x; v1 *= rs0*cs.y; v2 *= rs0*cs.z; v3 *= rs0*cs.w; }
                unsigned h0, l0, h1, l1;
                bf16split(v0, v1, h0, l0);
                bf16split(v2, v3, h1, l1);
                AsH[cur][rg0*16 + a0] = h0; AsL[cur][rg0*16 + a0] = l0;
                AsH[cur][rg0*16 + a1] = h1; AsL[cur][rg0*16 + a1] = l1;
            }
            {
                float v0 = pa1.x, v1 = pa1.y, v2 = pa1.z, v3 = pa1.w;
                if (MODE == 0) { v0 *= rs1*cs.x; v1 *= rs1*cs.y; v2 *= rs1*cs.z; v3 *= rs1*cs.w; }
                unsigned h0, l0, h1, l1;
                bf16split(v0, v1, h0, l0);
                bf16split(v2, v3, h1, l1);
                int rg1 = rg0 + 32;
                AsH[cur][rg1*16 + a0] = h0; AsL[cur][rg1*16 + a0] = l0;
                AsH[cur][rg1*16 + a1] = h1; AsL[cur][rg1*16 + a1] = l1;
            }
        }
        if (pre) cpwait<1>(); else cpwait<0>();
        __syncthreads();
        {
            int swg = (g >> 1) & 3;
            int txA = tig ^ swg;
            uint4 fH[4], fL[4];
#pragma unroll
            for (int mt = 0; mt < 4; mt++) {
                int rg = g | ((wm*4 + mt) << 3);
                fH[mt] = ((const uint4*)AsH[cur])[rg*4 + txA];
                fL[mt] = ((const uint4*)AsL[cur])[rg*4 + txA];
            }
#pragma unroll
            for (int nt = 0; nt < 4; nt++) {
                int nb = wn*32 + nt*8 + g;
                uint4 fB = ((const uint4*)Bs[cur])[nb*4 + tig];
                unsigned bH[2] = {fB.x, fB.y};
                unsigned bL[2] = {fB.z, fB.w};
#pragma unroll
                for (int mt = 0; mt < 4; mt++) {
                    mma_bf16(acc[mt][nt], (const unsigned*)&fH[mt], bH);
                    mma_bf16(acc[mt][nt], (const unsigned*)&fL[mt], bH);
                    mma_bf16(acc[mt][nt], (const unsigned*)&fH[mt], bL);
                }
            }
        }
        __syncthreads();
        pa0 = na0; pa1 = na1;
    }

    if (MODE == 0) {
#pragma unroll
        for (int mt = 0; mt < 4; mt++) {
#pragma unroll
            for (int nt = 0; nt < 4; nt++) {
                int r = row0 + wm*64 + mt*16 + g;
                int c = bx*128 + wn*32 + nt*8 + tig*2;
                float* pc0 = &C[(size_t)r*N + c];
                float* pc1 = &C[(size_t)(r+8)*N + c];
                pc0[0] = acc[mt][nt][0]; pc0[1] = acc[mt][nt][1];
                pc1[0] = acc[mt][nt][2]; pc1[1] = acc[mt][nt][3];
            }
        }
    } else {
        float* rsm = (float*)AsH;
        float sq[4][2];
#pragma unroll
        for (int mt = 0; mt < 4; mt++) { sq[mt][0] = 0.f; sq[mt][1] = 0.f; }
#pragma unroll
        for (int mt = 0; mt < 4; mt++) {
#pragma unroll
            for (int nt = 0; nt < 4; nt++) {
                int r = row0 + wm*64 + mt*16 + g;
                int c = wn*32 + nt*8 + tig*2;
                float* pc0 = &C[(size_t)r*N + c];
                float* pc1 = &C[(size_t)(r+8)*N + c];
                float f00 = pc0[0] + acc[mt][nt][0];
                float f01 = pc0[1] + acc[mt][nt][1];
                float f10 = pc1[0] + acc[mt][nt][2];
                float f11 = pc1[1] + acc[mt][nt][3];
                pc0[0] = f00; pc0[1] = f01;
                pc1[0] = f10; pc1[1] = f11;
                sq[mt][0] += f00*f00 + f01*f01;
                sq[mt][1] += f10*f10 + f11*f11;
            }
        }
#pragma unroll
        for (int mt = 0; mt < 4; mt++) {
#pragma unroll
            for (int hf = 0; hf < 2; hf++) {
                float v = sq[mt][hf];
                v += __shfl_xor_sync(0xffffffff, v, 1);
                v += __shfl_xor_sync(0xffffffff, v, 2);
                if (tig == 0) rsm[(wm*64 + mt*16 + g + hf*8)*4 + wn] = v;
            }
        }
        __syncthreads();
        if (tid < 128) {
            float s = rsm[tid*4] + rsm[tid*4+1] + rsm[tid*4+2] + rsm[tid*4+3];
            g_rstd[row0 + tid] = rsqrtf(s*(1.f/DMODEL) + 1e-5f);
        }
    }
}

// ---------------- 5. fused conv+silu + xproj + dt + scan + silu(z), f32x2 core ----------------
#define SMEM_MID ((40*260 + 32*260 + 32*260 + 32*40)*4)

__global__ __launch_bounds__(256, 2) void k_mid(
    const float* __restrict__ xw, const float* __restrict__ dtw, const float* __restrict__ dtb,
    const float* __restrict__ cw, const float* __restrict__ cb,
    const float* __restrict__ alog, const float* __restrict__ dp)
{
    extern __shared__ float sm[];
    float* xwT  = sm;                   // [40][260]
    float* uS   = sm + 40*260;          // [32][260]
    float* zS   = uS + 32*260;          // [32][260]
    float* dbcS = zS + 32*260;          // [32][40]

    int m = blockIdx.x, tid = threadIdx.x;
    int rloc = tid >> 3, cg = tid & 7;

    for (int i = tid; i < 256*40; i += 256) {
        int k = i/40, c = i - k*40;
        xwT[c*260 + k] = xw[i];
    }

    float w0 = cw[tid*4+0], w1 = cw[tid*4+1], w2 = cw[tid*4+2], w3 = cw[tid*4+3];
    float cbv = cb[tid];
    u64 dw2[4];
#pragma unroll
    for (int k = 0; k < 4; k++) dw2[k] = pack2(dtw[(2*k)*DI2 + tid], dtw[(2*k+1)*DI2 + tid]);
    float db = dtb[tid];
    float A[16];
#pragma unroll
    for (int s = 0; s < 16; s++) A[s] = -__expf(alog[tid*16 + s]);
    float A0 = A[0];
    bool fast = true;
#pragma unroll
    for (int s = 1; s < 16; s++) {
        float tgt = (float)(s+1)*A0;
        if (fabsf(A[s] - tgt) > 1e-4f*fabsf(tgt)) fast = false;
    }
    float Dv = dp[tid];
    u64 h2[8];
#pragma unroll
    for (int j = 0; j < 8; j++) h2[j] = 0ull;
    float hs[16];
#pragma unroll
    for (int s = 0; s < 16; s++) hs[s] = 0.f;
    float x0 = 0.f, x1 = 0.f, x2 = 0.f;
    const float* uz = g_uz + (size_t)m*NSEQ*512;
    float* yp = g_y + (size_t)m*NSEQ*DI2;
    __syncthreads();

    for (int n0 = 0; n0 < NSEQ; n0 += 32) {
        int CN = min(32, NSEQ - n0);
        float xv[32];
#pragma unroll
        for (int n = 0; n < 32; n++)
            xv[n] = (n < CN) ? uz[(size_t)(n0+n)*512 + tid] : 0.f;
#pragma unroll
        for (int n = 0; n < 32; n++)
            zS[n*260 + tid] = (n < CN) ? uz[(size_t)(n0+n)*512 + DI2 + tid] : 0.f;
#pragma unroll
        for (int n = 0; n < 32; n++) {
            float v = fmaf(x0, w0, fmaf(x1, w1, fmaf(x2, w2, fmaf(xv[n], w3, cbv))));
            uS[n*260 + tid] = __fdividef(v, 1.f + __expf(-v));
            x0 = x1; x1 = x2; x2 = xv[n];
        }
        __syncthreads();
        // --- xproj 256 -> 40, f32x2 pairs over k ---
        if (rloc < CN) {
            u64 acc2[5];
#pragma unroll
            for (int u = 0; u < 5; u++) acc2[u] = 0ull;
            const float4* ur4 = (const float4*)(uS + rloc*260);
#pragma unroll 8
            for (int k4 = 0; k4 < 64; k4++) {
                float4 a4 = ur4[k4];
                u64 ap0 = pack2(a4.x, a4.y);
                u64 ap1 = pack2(a4.z, a4.w);
#pragma unroll
                for (int u = 0; u < 5; u++) {
                    float4 w4 = ((const float4*)(xwT + (cg*5 + u)*260))[k4];
                    acc2[u] = fma2(ap0, pack2(w4.x, w4.y), acc2[u]);
                    acc2[u] = fma2(ap1, pack2(w4.z, w4.w), acc2[u]);
                }
            }
#pragma unroll
            for (int u = 0; u < 5; u++) {
                float lo, hi; unpack2(acc2[u], lo, hi);
                dbcS[rloc*40 + cg*5 + u] = lo + hi;
            }
        }
        __syncthreads();
        // --- delta + scan + silu(z), f32x2 ---
#pragma unroll 4
        for (int n = 0; n < 32; n++) {
            if (n < CN) {
                const ulonglong2* dq = (const ulonglong2*)(dbcS + n*40);
                ulonglong2 dtq0 = dq[0], dtq1 = dq[1];          // dt pairs
                ulonglong2 bq0 = dq[2], bq1 = dq[3], bq2 = dq[4], bq3 = dq[5];
                ulonglong2 cq0 = dq[6], cq1 = dq[7], cq2 = dq[8], cq3 = dq[9];
                u64 bb2[8] = {bq0.x, bq0.y, bq1.x, bq1.y, bq2.x, bq2.y, bq3.x, bq3.y};
                u64 cc2[8] = {cq0.x, cq0.y, cq1.x, cq1.y, cq2.x, cq2.y, cq3.x, cq3.y};
                u64 sd2 = fma2(dtq0.x, dw2[0], 0ull);
                sd2 = fma2(dtq0.y, dw2[1], sd2);
                sd2 = fma2(dtq1.x, dw2[2], sd2);
                sd2 = fma2(dtq1.y, dw2[3], sd2);
                float slo, shi; unpack2(sd2, slo, shi);
                float sdt = db + slo + shi;
                float d = fmaxf(sdt, 0.f) + __logf(1.f + __expf(-fabsf(sdt)));
                float u = uS[n*260 + tid];
                float dlu = d*u;
                u64 dlu2 = pack2(dlu, dlu);
                u64 acc2a = 0ull, acc2b = 0ull;
                if (fast) {
                    float q = __expf(d*A0);
                    float q2 = q*q;
                    u64 qq = pack2(q2, q2);
                    u64 p2 = pack2(q, q2);
#pragma unroll
                    for (int j = 0; j < 8; j++) {
                        h2[j] = fma2(p2, h2[j], mul2(dlu2, bb2[j]));
                        if (j & 1) acc2b = fma2(h2[j], cc2[j], acc2b);
                        else       acc2a = fma2(h2[j], cc2[j], acc2a);
                        p2 = mul2(p2, qq);
                    }
                } else {
#pragma unroll
                    for (int j = 0; j < 8; j++) {
                        u64 dA2 = pack2(__expf(d*A[2*j]), __expf(d*A[2*j+1]));
                        h2[j] = fma2(dA2, h2[j], mul2(dlu2, bb2[j]));
                        if (j & 1) acc2b = fma2(h2[j], cc2[j], acc2b);
                        else       acc2a = fma2(h2[j], cc2[j], acc2a);
                    }
                }
                float e0, e1, e2, e3;
                unpack2(acc2a, e0, e1);
                unpack2(acc2b, e2, e3);
                float accy = (e0 + e1) + (e2 + e3);
                float z = zS[n*260 + tid];
                float sz = __fdividef(z, 1.f + __expf(-z));
                yp[(size_t)(n0+n)*DI2 + tid] = (accy + u*Dv) * sz;
            }
        }
        __syncthreads();
    }
    (void)hs;
}

// ---------------- 6. final rms + bb dot ----------------
__global__ void k_final(const float* __restrict__ fnw, const float* __restrict__ bbw,
                        const float* __restrict__ bbb) {
    int m = blockIdx.x, t = threadIdx.x;   // 128 threads
    int w = t >> 5, lane = t & 31;
    __shared__ float rstdS[NSEQ];
    for (int n = w; n < NSEQ; n += 4) {
        const float* p = g_e + ((size_t)m*NSEQ + n)*DMODEL;
        float s = 0.f;
#pragma unroll
        for (int i = 0; i < 4; i++) { float v = p[lane + 32*i]; s = fmaf(v, v, s); }
#pragma unroll
        for (int o = 16; o; o >>= 1) s += __shfl_xor_sync(0xffffffff, s, o);
        if (lane == 0) rstdS[n] = rsqrtf(s*(1.f/DMODEL) + 1e-5f);
    }
    __syncthreads();
    float fn = fnw[t];
    float acc = 0.f;
    const float* ep = g_e + (size_t)m*NSEQ*DMODEL + t;
#pragma unroll 4
    for (int n = 0; n < NSEQ; n++)
        acc = fmaf(ep[(size_t)n*DMODEL]*rstdS[n]*fn, bbw[n*DMODEL + t], acc);
#pragma unroll
    for (int o = 16; o; o >>= 1) acc += __shfl_xor_sync(0xffffffff, acc, o);
    __shared__ float fr[4];
    if (lane == 0) fr[w] = acc;
    __syncthreads();
    if (t == 0) g_val[m] = fr[0] + fr[1] + fr[2] + fr[3] + bbb[0];
}

// ---------------- 7. head ----------------
__global__ void k_head(const float* __restrict__ hw, const float* __restrict__ hb,
                       float* __restrict__ out) {
    int t = threadIdx.x;  // 64
    int b = t >> 1, o = t & 1;
    float s = hb[o];
    for (int pd = 0; pd < 64; pd++) s = fmaf(g_val[b*64 + pd], hw[pd*2 + o], s);
    out[t] = s;
}

// ---------------- launch ----------------
extern "C" void kernel_launch(void* const* d_in, const int* in_sizes, int n_in,
                              void* d_out, int out_size) {
    const float* x       = (const float*)d_in[0];
    const float* proj_w  = (const float*)d_in[1];
    const float* proj_b  = (const float*)d_in[2];
    const float* ln_w    = (const float*)d_in[3];
    const float* ln_b    = (const float*)d_in[4];
    const float* patch_w = (const float*)d_in[5];
    const float* patch_b = (const float*)d_in[6];
    const float* in_w    = (const float*)d_in[7];
    const float* conv_w  = (const float*)d_in[8];
    const float* conv_b  = (const float*)d_in[9];
    const float* xproj_w = (const float*)d_in[10];
    const float* dt_w    = (const float*)d_in[11];
    const float* dt_b    = (const float*)d_in[12];
    const float* A_log   = (const float*)d_in[13];
    const float* Dp      = (const float*)d_in[14];
    const float* out_w   = (const float*)d_in[15];
    const float* norm_w  = (const float*)d_in[16];
    const float* fnorm_w = (const float*)d_in[17];
    const float* bb_w    = (const float*)d_in[18];
    const float* bb_b    = (const float*)d_in[19];
    const float* head_w  = (const float*)d_in[20];
    const float* head_b  = (const float*)d_in[21];

    cudaFuncSetAttribute(k_mid, cudaFuncAttributeMaxDynamicSharedMemorySize, SMEM_MID);

    unsigned *d_win, *d_wout;
    float *d_uzp, *d_ep, *d_yp;
    cudaGetSymbolAddress((void**)&d_win, g_wins);
    cudaGetSymbolAddress((void**)&d_wout, g_wouts);
    cudaGetSymbolAddress((void**)&d_uzp, g_uz);
    cudaGetSymbolAddress((void**)&d_ep, g_e);
    cudaGetSymbolAddress((void**)&d_yp, g_y);

    // launch #3 = gemm<0> (ncu capture slot)
    k_wsplit<<<(NLAYERS*(32768+16384))/256, 256>>>(in_w, out_w);
    k_proj_ln<<<BATCH*KLEN, 64>>>(x, proj_w, proj_b, ln_w, ln_b);
    k_patch<<<dim3(NSEQ, MROWS), DMODEL>>>(patch_w, patch_b);   // fused rms

    for (int l = 0; l < NLAYERS; l++) {
        k_gemm_tc<0><<<dim3(4, RTOT/128), 256>>>(d_ep, norm_w + l*DMODEL,
                                                 d_win + (size_t)l*65536, d_uzp);
        k_mid<<<MROWS, 256, SMEM_MID>>>(xproj_w + l*DI2*40, dt_w + l*DTRANK*DI2, dt_b + l*DI2,
                                        conv_w + l*DI2*DCONV, conv_b + l*DI2,
                                        A_log + l*DI2*DSTATE, Dp + l*DI2);
        k_gemm_tc<1><<<dim3(1, RTOT/128), 256>>>(d_yp, nullptr,
                                                 d_wout + (size_t)l*32768, d_ep);
    }

    k_final<<<MROWS, DMODEL>>>(fnorm_w, bb_w, bb_b);
    k_head<<<1, 64>>>(head_w, head_b, (float*)d_out);
}

// round 15
// speedup vs baseline: 1.0317x; 1.0317x over previous
#include <cuda_runtime.h>
#include <math.h>

// ---------------- problem constants ----------------
#define DIN     32
#define KLEN    512
#define PDIM    64
#define DMODEL  128
#define NLAYERS 4
#define PLEN    8
#define STRIDE  4
#define DI2     256
#define DSTATE  16
#define DCONV   4
#define DTRANK  8
#define NSEQ    127
#define BATCH   32
#define MROWS   (BATCH*PDIM)     // 2048
#define RTOT    (MROWS*NSEQ)     // 260096
#define NRB     (RTOT/128)       // 2032 row-blocks

// ---------------- scratch ----------------
__device__ float g_h[BATCH*KLEN*PDIM];
__device__ float g_e[RTOT*DMODEL];
__device__ float g_rstd[RTOT];
__device__ float g_uz[RTOT*2*DI2];
__device__ float g_y[RTOT*DI2];
__device__ unsigned g_wins[NLAYERS*65536];   // in_w bf16-pair images
__device__ unsigned g_wouts[NLAYERS*32768];  // out_w bf16-pair images
__device__ unsigned g_ea[NRB*16384];         // rms(e)*nw bf16 H/L image (gemm0 A operand)
__device__ float g_val[MROWS];

// ---------------- helpers ----------------
__device__ __forceinline__ unsigned bf16pair(float v0, float v1) {
    unsigned p;
    asm("cvt.rn.bf16x2.f32 %0, %1, %2;" : "=r"(p) : "f"(v1), "f"(v0));
    return p;
}
__device__ __forceinline__ void bf16split(float v0, float v1, unsigned& hp, unsigned& lp) {
    hp = bf16pair(v0, v1);
    float r0 = v0 - __uint_as_float(hp << 16);
    float r1 = v1 - __uint_as_float(hp & 0xffff0000u);
    lp = bf16pair(r0, r1);
}
__device__ __forceinline__ void mma_bf16(float* d, const unsigned* a, const unsigned* b) {
    asm volatile(
        "mma.sync.aligned.m16n8k16.row.col.f32.bf16.bf16.f32 "
        "{%0,%1,%2,%3}, {%4,%5,%6,%7}, {%8,%9}, {%0,%1,%2,%3};\n"
        : "+f"(d[0]), "+f"(d[1]), "+f"(d[2]), "+f"(d[3])
        : "r"(a[0]), "r"(a[1]), "r"(a[2]), "r"(a[3]), "r"(b[0]), "r"(b[1]));
}
__device__ __forceinline__ void cp16(unsigned smem, const void* gptr) {
    asm volatile("cp.async.cg.shared.global [%0], [%1], 16;\n" :: "r"(smem), "l"(gptr));
}
__device__ __forceinline__ unsigned s2u(const void* p) {
    return (unsigned)__cvta_generic_to_shared(p);
}
template<int NN> __device__ __forceinline__ void cpwait() {
    asm volatile("cp.async.wait_group %0;\n" :: "n"(NN));
}
// image slot for row r (0..127 within block), pair p (0..63): returns u32 index
// within the k-tile's 2048-word image (H half; L at +1024). kt = p>>3.
__device__ __forceinline__ int img_slot(int r, int pl) {
    int rg = (r & 7) | (((r >> 4) & 7) << 3);
    int rb3 = (r >> 3) & 1;
    int sw = (rg >> 1) & 3;
    return rg*16 + (((pl & 3) ^ sw) << 2) + (rb3 | ((pl >> 2) << 1));
}
// ---- packed f32x2 (sm_100+) ----
typedef unsigned long long u64;
__device__ __forceinline__ u64 pack2(float lo, float hi) {
    u64 r; asm("mov.b64 %0, {%1, %2};" : "=l"(r) : "f"(lo), "f"(hi)); return r;
}
__device__ __forceinline__ void unpack2(u64 v, float& lo, float& hi) {
    asm("mov.b64 {%0, %1}, %2;" : "=f"(lo), "=f"(hi) : "l"(v));
}
__device__ __forceinline__ u64 fma2(u64 a, u64 b, u64 c) {
    u64 d; asm("fma.rn.f32x2 %0, %1, %2, %3;" : "=l"(d) : "l"(a), "l"(b), "l"(c)); return d;
}
__device__ __forceinline__ u64 mul2(u64 a, u64 b) {
    u64 d; asm("mul.rn.f32x2 %0, %1, %2;" : "=l"(d) : "l"(a), "l"(b)); return d;
}

// ---------------- 1. weight pre-split (launch #0) ----------------
__global__ void k_wsplit(const float* __restrict__ in_w, const float* __restrict__ out_w) {
    int idx = blockIdx.x*256 + threadIdx.x;
    if (idx < NLAYERS*32768) {
        int l = idx >> 15;
        int e = idx & 32767;
        int pg = e >> 9, n = e & 511;
        const float* W = in_w + (size_t)l*65536;
        float v0 = W[(2*pg)*512 + n];
        float v1 = W[(2*pg+1)*512 + n];
        unsigned hp, lp; bf16split(v0, v1, hp, lp);
        int bx = n >> 7, nl = n & 127;
        int kt = pg >> 3, pl = pg & 7;
        int slotH = (pl >> 2) & 1;
        size_t base = (size_t)l*65536 + (size_t)(bx*8 + kt)*2048 + (size_t)(nl*4 + (pl & 3))*4;
        g_wins[base + slotH]     = hp;
        g_wins[base + 2 + slotH] = lp;
    } else {
        int idx2 = idx - NLAYERS*32768;
        if (idx2 < NLAYERS*16384) {
            int l = idx2 >> 14;
            int e = idx2 & 16383;
            int pg = e >> 7, n = e & 127;
            const float* W = out_w + (size_t)l*32768;
            float v0 = W[(2*pg)*128 + n];
            float v1 = W[(2*pg+1)*128 + n];
            unsigned hp, lp; bf16split(v0, v1, hp, lp);
            int kt = pg >> 3, pl = pg & 7;
            int slotH = (pl >> 2) & 1;
            size_t base = (size_t)l*32768 + (size_t)kt*2048 + (size_t)(n*4 + (pl & 3))*4;
            g_wouts[base + slotH]     = hp;
            g_wouts[base + 2 + slotH] = lp;
        }
    }
}

// ---------------- 2. x@proj_w + b, LayerNorm (launch #1) ----------------
__global__ void k_proj_ln(const float* __restrict__ x, const float* __restrict__ pw,
                          const float* __restrict__ pb, const float* __restrict__ lw,
                          const float* __restrict__ lb) {
    int row = blockIdx.x;
    int t = threadIdx.x;
    __shared__ float xs[DIN];
    __shared__ float r1[64], r2[64];
    if (t < DIN) xs[t] = x[row*DIN + t];
    __syncthreads();
    float acc = pb[t];
#pragma unroll
    for (int i = 0; i < DIN; i++) acc = fmaf(xs[i], pw[i*PDIM + t], acc);
    r1[t] = acc; r2[t] = acc*acc;
    __syncthreads();
    for (int o = 32; o; o >>= 1) {
        if (t < o) { r1[t] += r1[t+o]; r2[t] += r2[t+o]; }
        __syncthreads();
    }
    float mu  = r1[0] * (1.f/64.f);
    float var = r2[0] * (1.f/64.f) - mu*mu;
    g_h[row*PDIM + t] = (acc - mu) * rsqrtf(var + 1e-5f) * lw[t] + lb[t];
}

// ---------------- 3. patch embed + fused rms + layer-0 A-image (launch #2) ----------------
__global__ void k_patch(const float* __restrict__ pw, const float* __restrict__ pb,
                        const float* __restrict__ nw0) {
    int n = blockIdx.x, m = blockIdx.y;
    int t = threadIdx.x;                 // 0..127
    int w = t >> 5, lane = t & 31;
    __shared__ float hv[PLEN];
    __shared__ float red[4];
    __shared__ float eS[DMODEL];
    int b = m >> 6, pd = m & 63;
    if (t < PLEN) hv[t] = g_h[(b*KLEN + n*STRIDE + t)*PDIM + pd];
    __syncthreads();
    float acc = pb[t];
#pragma unroll
    for (int p = 0; p < PLEN; p++) acc = fmaf(hv[p], pw[p*DMODEL + t], acc);
    size_t R = (size_t)m*NSEQ + n;
    g_e[R*DMODEL + t] = acc;
    eS[t] = acc;
    float s = acc*acc;
#pragma unroll
    for (int o = 16; o; o >>= 1) s += __shfl_xor_sync(0xffffffff, s, o);
    if (lane == 0) red[w] = s;
    __syncthreads();
    float rstdv = rsqrtf((red[0] + red[1] + red[2] + red[3])*(1.f/DMODEL) + 1e-5f);
    if (t == 0) g_rstd[R] = rstdv;
    if (t < 64) {
        int p = t;                       // pair 0..63
        float v0 = eS[2*p]   * rstdv * nw0[2*p];
        float v1 = eS[2*p+1] * rstdv * nw0[2*p+1];
        unsigned hp, lp; bf16split(v0, v1, hp, lp);
        int by = (int)(R >> 7);
        int r  = (int)(R & 127);
        int kt = p >> 3;
        int slot = img_slot(r, p & 7);
        unsigned* img = g_ea + (size_t)by*16384 + (size_t)kt*2048;
        img[slot]        = hp;
        img[slot + 1024] = lp;
    }
}

// ---------------- 4. e -> gemm0 A-image (layers 1..3) ----------------
#define SMEM_ESPL (16384*4)
__global__ void k_esplit(const float* __restrict__ nw) {
    extern __shared__ unsigned simg[];   // 16384 u32 image for this row-block
    int by = blockIdx.x, tid = threadIdx.x;
    int r = tid >> 1, half = tid & 1;
    int R = by*128 + r;
    float rs = g_rstd[R];
    const float4* ep  = (const float4*)(g_e + (size_t)R*DMODEL + half*64);
    const float4* nwp = (const float4*)(nw + half*64);
    int rg = (r & 7) | (((r >> 4) & 7) << 3);
    int rb3 = (r >> 3) & 1;
    int sw = (rg >> 1) & 3;
#pragma unroll
    for (int q = 0; q < 16; q++) {       // 16 float4 = 64 cols = 32 pairs
        float4 v = ep[q];
        float4 wv = nwp[q];
        v.x *= rs*wv.x; v.y *= rs*wv.y; v.z *= rs*wv.z; v.w *= rs*wv.w;
        unsigned h0, l0, h1, l1;
        bf16split(v.x, v.y, h0, l0);
        bf16split(v.z, v.w, h1, l1);
        int p0 = half*32 + q*2;
#pragma unroll
        for (int u = 0; u < 2; u++) {
            int p = p0 + u;
            int kt = p >> 3, pl = p & 7;
            int slot = rg*16 + (((pl & 3) ^ sw) << 2) + (rb3 | ((pl >> 2) << 1));
            unsigned hh = u ? h1 : h0, ll = u ? l1 : l0;
            simg[kt*2048 + slot]        = hh;
            simg[kt*2048 + 1024 + slot] = ll;
        }
    }
    __syncthreads();
    float4* dst = (float4*)g_ea + (size_t)by*4096;
    const float4* src = (const float4*)simg;
#pragma unroll
    for (int i = 0; i < 16; i++) dst[tid + i*256] = src[tid + i*256];
}

// ---------------- 5. bf16x2 (3-product) GEMM ----------------
// MODE 0: g_uz = image(rms(e)*nw) @ in_w  (K=128, N=512); A via cp.async image
// MODE 1: g_e += y @ out_w; epilogue writes g_rstd
template<int MODE>
__global__ __launch_bounds__(256, 2) void k_gemm_tc(const float* __restrict__ A,
                                                    const unsigned* __restrict__ Aimg,
                                                    const unsigned* __restrict__ Bp,
                                                    float* __restrict__ C) {
    constexpr int N  = (MODE == 0) ? 512 : 128;
    constexpr int K  = (MODE == 0) ? 128 : 256;
    constexpr int KT = K/16;

    __shared__ __align__(16) unsigned As[2][2048], Bs[2][2048];

    int tid = threadIdx.x;
    int wid = tid >> 5, lane = tid & 31;
    int wm = wid >> 2, wn = wid & 3;
    int g = lane >> 2, tig = lane & 3;
    int row0 = blockIdx.y * 128;
    int bx = blockIdx.x;
    const float4* Bg = (const float4*)Bp + (size_t)bx*KT*512;

    float acc[4][4][4];
#pragma unroll
    for (int mt = 0; mt < 4; mt++)
#pragma unroll
        for (int nt = 0; nt < 4; nt++)
#pragma unroll
            for (int j = 0; j < 4; j++) acc[mt][nt][j] = 0.f;

    // MODE1 A-staging state
    int rA = tid >> 2;
    int kq = (tid & 3)*4;
    int p0 = kq >> 1;
    int rg0 = (rA & 7) | ((rA >> 4) << 3);
    int rb3 = (rA >> 3) & 1;
    int sw  = (rg0 >> 1) & 3;
    int a0 = (((p0 & 3) ^ sw) << 2) + (rb3 | (((p0 >> 2) & 1) << 1));
    int p1i = p0 + 1;
    int a1 = (((p1i & 3) ^ sw) << 2) + (rb3 | (((p1i >> 2) & 1) << 1));

    const float4* Ag = (MODE == 0) ? ((const float4*)Aimg + (size_t)blockIdx.y*KT*512) : nullptr;

    float4 pa0, pa1;
    if (MODE == 0) {
        cp16(s2u(&As[0][tid*4]),       Ag + tid);
        cp16(s2u(&As[0][(tid+256)*4]), Ag + tid + 256);
        cp16(s2u(&Bs[0][tid*4]),       Bg + tid);
        cp16(s2u(&Bs[0][(tid+256)*4]), Bg + tid + 256);
        asm volatile("cp.async.commit_group;\n");
    } else {
        cp16(s2u(&Bs[0][tid*4]),       Bg + tid);
        cp16(s2u(&Bs[0][(tid+256)*4]), Bg + tid + 256);
        asm volatile("cp.async.commit_group;\n");
        pa0 = *(const float4*)&A[(size_t)(row0 + rA)*K + kq];
        pa1 = *(const float4*)&A[(size_t)(row0 + rA + 64)*K + kq];
    }

    for (int kt = 0; kt < KT; kt++) {
        int cur = kt & 1, nxt = cur ^ 1;
        bool pre = (kt + 1 < KT);
        if (pre) {
            if (MODE == 0) {
                const float4* asrc = Ag + (size_t)(kt+1)*512;
                cp16(s2u(&As[nxt][tid*4]),       asrc + tid);
                cp16(s2u(&As[nxt][(tid+256)*4]), asrc + tid + 256);
            }
            const float4* src = Bg + (size_t)(kt+1)*512;
            cp16(s2u(&Bs[nxt][tid*4]),       src + tid);
            cp16(s2u(&Bs[nxt][(tid+256)*4]), src + tid + 256);
            asm volatile("cp.async.commit_group;\n");
        }
        if (MODE == 1) {
            float4 na0 = pa0, na1 = pa1;
            if (pre) {
                int k0n = (kt+1)*16;
                na0 = *(const float4*)&A[(size_t)(row0 + rA)*K + k0n + kq];
                na1 = *(const float4*)&A[(size_t)(row0 + rA + 64)*K + k0n + kq];
            }
            {
                unsigned h0, l0, h1, l1;
                bf16split(pa0.x, pa0.y, h0, l0);
                bf16split(pa0.z, pa0.w, h1, l1);
                As[cur][rg0*16 + a0] = h0; As[cur][1024 + rg0*16 + a0] = l0;
                As[cur][rg0*16 + a1] = h1; As[cur][1024 + rg0*16 + a1] = l1;
            }
            {
                unsigned h0, l0, h1, l1;
                bf16split(pa1.x, pa1.y, h0, l0);
                bf16split(pa1.z, pa1.w, h1, l1);
                int rg1 = rg0 + 32;
                As[cur][rg1*16 + a0] = h0; As[cur][1024 + rg1*16 + a0] = l0;
                As[cur][rg1*16 + a1] = h1; As[cur][1024 + rg1*16 + a1] = l1;
            }
            pa0 = na0; pa1 = na1;
        }
        if (pre) cpwait<1>(); else cpwait<0>();
        __syncthreads();
        {
            int swg = (g >> 1) & 3;
            int txA = tig ^ swg;
            uint4 fH[4], fL[4];
#pragma unroll
            for (int mt = 0; mt < 4; mt++) {
                int rg = g | ((wm*4 + mt) << 3);
                fH[mt] = ((const uint4*)As[cur])[rg*4 + txA];
                fL[mt] = ((const uint4*)As[cur])[256 + rg*4 + txA];
            }
#pragma unroll
            for (int nt = 0; nt < 4; nt++) {
                int nb = wn*32 + nt*8 + g;
                uint4 fB = ((const uint4*)Bs[cur])[nb*4 + tig];
                unsigned bH[2] = {fB.x, fB.y};
                unsigned bL[2] = {fB.z, fB.w};
#pragma unroll
                for (int mt = 0; mt < 4; mt++) {
                    mma_bf16(acc[mt][nt], (const unsigned*)&fH[mt], bH);
                    mma_bf16(acc[mt][nt], (const unsigned*)&fL[mt], bH);
                    mma_bf16(acc[mt][nt], (const unsigned*)&fH[mt], bL);
                }
            }
        }
        __syncthreads();
    }

    if (MODE == 0) {
#pragma unroll
        for (int mt = 0; mt < 4; mt++) {
#pragma unroll
            for (int nt = 0; nt < 4; nt++) {
                int r = row0 + wm*64 + mt*16 + g;
                int c = bx*128 + wn*32 + nt*8 + tig*2;
                float* pc0 = &C[(size_t)r*N + c];
                float* pc1 = &C[(size_t)(r+8)*N + c];
                pc0[0] = acc[mt][nt][0]; pc0[1] = acc[mt][nt][1];
                pc1[0] = acc[mt][nt][2]; pc1[1] = acc[mt][nt][3];
            }
        }
    } else {
        float* rsm = (float*)As;
        float sq[4][2];
#pragma unroll
        for (int mt = 0; mt < 4; mt++) { sq[mt][0] = 0.f; sq[mt][1] = 0.f; }
#pragma unroll
        for (int mt = 0; mt < 4; mt++) {
#pragma unroll
            for (int nt = 0; nt < 4; nt++) {
                int r = row0 + wm*64 + mt*16 + g;
                int c = wn*32 + nt*8 + tig*2;
                float* pc0 = &C[(size_t)r*N + c];
                float* pc1 = &C[(size_t)(r+8)*N + c];
                float f00 = pc0[0] + acc[mt][nt][0];
                float f01 = pc0[1] + acc[mt][nt][1];
                float f10 = pc1[0] + acc[mt][nt][2];
                float f11 = pc1[1] + acc[mt][nt][3];
                pc0[0] = f00; pc0[1] = f01;
                pc1[0] = f10; pc1[1] = f11;
                sq[mt][0] += f00*f00 + f01*f01;
                sq[mt][1] += f10*f10 + f11*f11;
            }
        }
#pragma unroll
        for (int mt = 0; mt < 4; mt++) {
#pragma unroll
            for (int hf = 0; hf < 2; hf++) {
                float v = sq[mt][hf];
                v += __shfl_xor_sync(0xffffffff, v, 1);
                v += __shfl_xor_sync(0xffffffff, v, 2);
                if (tig == 0) rsm[(wm*64 + mt*16 + g + hf*8)*4 + wn] = v;
            }
        }
        __syncthreads();
        if (tid < 128) {
            float s = rsm[tid*4] + rsm[tid*4+1] + rsm[tid*4+2] + rsm[tid*4+3];
            g_rstd[row0 + tid] = rsqrtf(s*(1.f/DMODEL) + 1e-5f);
        }
    }
}

// ---------------- 6. fused conv+silu + xproj + dt + scan + silu(z), f32x2 core ----------------
#define SMEM_MID ((40*260 + 32*260 + 32*260 + 32*40)*4)

__global__ __launch_bounds__(256, 2) void k_mid(
    const float* __restrict__ xw, const float* __restrict__ dtw, const float* __restrict__ dtb,
    const float* __restrict__ cw, const float* __restrict__ cb,
    const float* __restrict__ alog, const float* __restrict__ dp)
{
    extern __shared__ float sm[];
    float* xwT  = sm;                   // [40][260]
    float* uS   = sm + 40*260;          // [32][260]
    float* zS   = uS + 32*260;          // [32][260]
    float* dbcS = zS + 32*260;          // [32][40]

    int m = blockIdx.x, tid = threadIdx.x;
    int rloc = tid >> 3, cg = tid & 7;

    for (int i = tid; i < 256*40; i += 256) {
        int k = i/40, c = i - k*40;
        xwT[c*260 + k] = xw[i];
    }

    float w0 = cw[tid*4+0], w1 = cw[tid*4+1], w2 = cw[tid*4+2], w3 = cw[tid*4+3];
    float cbv = cb[tid];
    u64 dw2[4];
#pragma unroll
    for (int k = 0; k < 4; k++) dw2[k] = pack2(dtw[(2*k)*DI2 + tid], dtw[(2*k+1)*DI2 + tid]);
    float db = dtb[tid];
    float A[16];
#pragma unroll
    for (int s = 0; s < 16; s++) A[s] = -__expf(alog[tid*16 + s]);
    float A0 = A[0];
    bool fast = true;
#pragma unroll
    for (int s = 1; s < 16; s++) {
        float tgt = (float)(s+1)*A0;
        if (fabsf(A[s] - tgt) > 1e-4f*fabsf(tgt)) fast = false;
    }
    float Dv = dp[tid];
    u64 h2[8];
#pragma unroll
    for (int j = 0; j < 8; j++) h2[j] = 0ull;
    float x0 = 0.f, x1 = 0.f, x2 = 0.f;
    const float* uz = g_uz + (size_t)m*NSEQ*512;
    float* yp = g_y + (size_t)m*NSEQ*DI2;
    __syncthreads();

    for (int n0 = 0; n0 < NSEQ; n0 += 32) {
        int CN = min(32, NSEQ - n0);
        float xv[32];
#pragma unroll
        for (int n = 0; n < 32; n++)
            xv[n] = (n < CN) ? uz[(size_t)(n0+n)*512 + tid] : 0.f;
#pragma unroll
        for (int n = 0; n < 32; n++)
            zS[n*260 + tid] = (n < CN) ? uz[(size_t)(n0+n)*512 + DI2 + tid] : 0.f;
#pragma unroll
        for (int n = 0; n < 32; n++) {
            float v = fmaf(x0, w0, fmaf(x1, w1, fmaf(x2, w2, fmaf(xv[n], w3, cbv))));
            uS[n*260 + tid] = __fdividef(v, 1.f + __expf(-v));
            x0 = x1; x1 = x2; x2 = xv[n];
        }
        __syncthreads();
        if (rloc < CN) {
            u64 acc2[5];
#pragma unroll
            for (int u = 0; u < 5; u++) acc2[u] = 0ull;
            const float4* ur4 = (const float4*)(uS + rloc*260);
#pragma unroll 8
            for (int k4 = 0; k4 < 64; k4++) {
                float4 a4 = ur4[k4];
                u64 ap0 = pack2(a4.x, a4.y);
                u64 ap1 = pack2(a4.z, a4.w);
#pragma unroll
                for (int u = 0; u < 5; u++) {
                    float4 w4 = ((const float4*)(xwT + (cg*5 + u)*260))[k4];
                    acc2[u] = fma2(ap0, pack2(w4.x, w4.y), acc2[u]);
                    acc2[u] = fma2(ap1, pack2(w4.z, w4.w), acc2[u]);
                }
            }
#pragma unroll
            for (int u = 0; u < 5; u++) {
                float lo, hi; unpack2(acc2[u], lo, hi);
                dbcS[rloc*40 + cg*5 + u] = lo + hi;
            }
        }
        __syncthreads();
#pragma unroll 4
        for (int n = 0; n < 32; n++) {
            if (n < CN) {
                const ulonglong2* dq = (const ulonglong2*)(dbcS + n*40);
                ulonglong2 dtq0 = dq[0], dtq1 = dq[1];
                ulonglong2 bq0 = dq[2], bq1 = dq[3], bq2 = dq[4], bq3 = dq[5];
                ulonglong2 cq0 = dq[6], cq1 = dq[7], cq2 = dq[8], cq3 = dq[9];
                u64 bb2[8] = {bq0.x, bq0.y, bq1.x, bq1.y, bq2.x, bq2.y, bq3.x, bq3.y};
                u64 cc2[8] = {cq0.x, cq0.y, cq1.x, cq1.y, cq2.x, cq2.y, cq3.x, cq3.y};
                u64 sd2 = fma2(dtq0.x, dw2[0], 0ull);
                sd2 = fma2(dtq0.y, dw2[1], sd2);
                sd2 = fma2(dtq1.x, dw2[2], sd2);
                sd2 = fma2(dtq1.y, dw2[3], sd2);
                float slo, shi; unpack2(sd2, slo, shi);
                float sdt = db + slo + shi;
                float d = fmaxf(sdt, 0.f) + __logf(1.f + __expf(-fabsf(sdt)));
                float u = uS[n*260 + tid];
                float dlu = d*u;
                u64 dlu2 = pack2(dlu, dlu);
                u64 acc2a = 0ull, acc2b = 0ull;
                if (fast) {
                    float q = __expf(d*A0);
                    float q2 = q*q;
                    u64 qq = pack2(q2, q2);
                    u64 p2 = pack2(q, q2);
#pragma unroll
                    for (int j = 0; j < 8; j++) {
                        h2[j] = fma2(p2, h2[j], mul2(dlu2, bb2[j]));
                        if (j & 1) acc2b = fma2(h2[j], cc2[j], acc2b);
                        else       acc2a = fma2(h2[j], cc2[j], acc2a);
                        p2 = mul2(p2, qq);
                    }
                } else {
#pragma unroll
                    for (int j = 0; j < 8; j++) {
                        u64 dA2 = pack2(__expf(d*A[2*j]), __expf(d*A[2*j+1]));
                        h2[j] = fma2(dA2, h2[j], mul2(dlu2, bb2[j]));
                        if (j & 1) acc2b = fma2(h2[j], cc2[j], acc2b);
                        else       acc2a = fma2(h2[j], cc2[j], acc2a);
                    }
                }
                float e0, e1, e2, e3;
                unpack2(acc2a, e0, e1);
                unpack2(acc2b, e2, e3);
                float accy = (e0 + e1) + (e2 + e3);
                float z = zS[n*260 + tid];
                float sz = __fdividef(z, 1.f + __expf(-z));
                yp[(size_t)(n0+n)*DI2 + tid] = (accy + u*Dv) * sz;
            }
        }
        __syncthreads();
    }
}

// ---------------- 7. final rms + bb dot ----------------
__global__ void k_final(const float* __restrict__ fnw, const float* __restrict__ bbw,
                        const float* __restrict__ bbb) {
    int m = blockIdx.x, t = threadIdx.x;   // 128 threads
    int w = t >> 5, lane = t & 31;
    __shared__ float rstdS[NSEQ];
    for (int n = w; n < NSEQ; n += 4) {
        const float* p = g_e + ((size_t)m*NSEQ + n)*DMODEL;
        float s = 0.f;
#pragma unroll
        for (int i = 0; i < 4; i++) { float v = p[lane + 32*i]; s = fmaf(v, v, s); }
#pragma unroll
        for (int o = 16; o; o >>= 1) s += __shfl_xor_sync(0xffffffff, s, o);
        if (lane == 0) rstdS[n] = rsqrtf(s*(1.f/DMODEL) + 1e-5f);
    }
    __syncthreads();
    float fn = fnw[t];
    float acc = 0.f;
    const float* ep = g_e + (size_t)m*NSEQ*DMODEL + t;
#pragma unroll 4
    for (int n = 0; n < NSEQ; n++)
        acc = fmaf(ep[(size_t)n*DMODEL]*rstdS[n]*fn, bbw[n*DMODEL + t], acc);
#pragma unroll
    for (int o = 16; o; o >>= 1) acc += __shfl_xor_sync(0xffffffff, acc, o);
    __shared__ float fr[4];
    if (lane == 0) fr[w] = acc;
    __syncthreads();
    if (t == 0) g_val[m] = fr[0] + fr[1] + fr[2] + fr[3] + bbb[0];
}

// ---------------- 8. head ----------------
__global__ void k_head(const float* __restrict__ hw, const float* __restrict__ hb,
                       float* __restrict__ out) {
    int t = threadIdx.x;  // 64
    int b = t >> 1, o = t & 1;
    float s = hb[o];
    for (int pd = 0; pd < 64; pd++) s = fmaf(g_val[b*64 + pd], hw[pd*2 + o], s);
    out[t] = s;
}

// ---------------- launch ----------------
extern "C" void kernel_launch(void* const* d_in, const int* in_sizes, int n_in,
                              void* d_out, int out_size) {
    const float* x       = (const float*)d_in[0];
    const float* proj_w  = (const float*)d_in[1];
    const float* proj_b  = (const float*)d_in[2];
    const float* ln_w    = (const float*)d_in[3];
    const float* ln_b    = (const float*)d_in[4];
    const float* patch_w = (const float*)d_in[5];
    const float* patch_b = (const float*)d_in[6];
    const float* in_w    = (const float*)d_in[7];
    const float* conv_w  = (const float*)d_in[8];
    const float* conv_b  = (const float*)d_in[9];
    const float* xproj_w = (const float*)d_in[10];
    const float* dt_w    = (const float*)d_in[11];
    const float* dt_b    = (const float*)d_in[12];
    const float* A_log   = (const float*)d_in[13];
    const float* Dp      = (const float*)d_in[14];
    const float* out_w   = (const float*)d_in[15];
    const float* norm_w  = (const float*)d_in[16];
    const float* fnorm_w = (const float*)d_in[17];
    const float* bb_w    = (const float*)d_in[18];
    const float* bb_b    = (const float*)d_in[19];
    const float* head_w  = (const float*)d_in[20];
    const float* head_b  = (const float*)d_in[21];

    cudaFuncSetAttribute(k_mid, cudaFuncAttributeMaxDynamicSharedMemorySize, SMEM_MID);
    cudaFuncSetAttribute(k_esplit, cudaFuncAttributeMaxDynamicSharedMemorySize, SMEM_ESPL);

    unsigned *d_win, *d_wout, *d_ea;
    float *d_uzp, *d_ep, *d_yp;
    cudaGetSymbolAddress((void**)&d_win, g_wins);
    cudaGetSymbolAddress((void**)&d_wout, g_wouts);
    cudaGetSymbolAddress((void**)&d_ea, g_ea);
    cudaGetSymbolAddress((void**)&d_uzp, g_uz);
    cudaGetSymbolAddress((void**)&d_ep, g_e);
    cudaGetSymbolAddress((void**)&d_yp, g_y);

    // launch #3 = gemm<0> (ncu capture slot)
    k_wsplit<<<(NLAYERS*(32768+16384))/256, 256>>>(in_w, out_w);
    k_proj_ln<<<BATCH*KLEN, 64>>>(x, proj_w, proj_b, ln_w, ln_b);
    k_patch<<<dim3(NSEQ, MROWS), DMODEL>>>(patch_w, patch_b, norm_w);  // rms + layer-0 image

    for (int l = 0; l < NLAYERS; l++) {
        if (l > 0)
            k_esplit<<<NRB, 256, SMEM_ESPL>>>(norm_w + l*DMODEL);
        k_gemm_tc<0><<<dim3(4, NRB), 256>>>(nullptr, d_ea,
                                            d_win + (size_t)l*65536, d_uzp);
        k_mid<<<MROWS, 256, SMEM_MID>>>(xproj_w + l*DI2*40, dt_w + l*DTRANK*DI2, dt_b + l*DI2,
                                        conv_w + l*DI2*DCONV, conv_b + l*DI2,
                                        A_log + l*DI2*DSTATE, Dp + l*DI2);
        k_gemm_tc<1><<<dim3(1, NRB), 256>>>(d_yp, nullptr,
                                            d_wout + (size_t)l*32768, d_ep);
    }

    k_final<<<MROWS, DMODEL>>>(fnorm_w, bb_w, bb_b);
    k_head<<<1, 64>>>(head_w, head_b, (float*)d_out);
}